// round 3
// baseline (speedup 1.0000x reference)
#include <cuda_runtime.h>
#include <cuda_bf16.h>
#include <cstdint>

#define N_PTS 384
#define DIM 128
#define MARGIN 0.3f

// ---------------------------------------------------------------------------
// Fused triplet-loss kernel: one block per anchor, one thread per point.
// Phase 1: each thread computes dist(anchor, j) straight from embeddings
//          (anchor row staged in smem; embeddings L2-resident).
// Phase 2: warp-aggregated compaction into positive / negative distance lists.
// Phase 3: brute-force (p, n) pairs, block-reduce, atomicAdd into out[0..1].
// ---------------------------------------------------------------------------
__global__ __launch_bounds__(N_PTS) void fused_triplet_kernel(
    const float* __restrict__ E,
    const int* __restrict__ labels,
    float* __restrict__ out) {

    const int i = blockIdx.x;   // anchor
    const int t = threadIdx.x;  // point j == t
    const int lane = t & 31;
    const int warp = t >> 5;    // 12 warps

    __shared__ float anchor[DIM];
    __shared__ float spos[N_PTS];
    __shared__ float sneg[N_PTS];
    __shared__ int cnts[2];          // [0]=P, [1]=M
    __shared__ float wl[12], wc[12];

    if (t < 2) cnts[t] = 0;
    if (t < DIM) anchor[t] = E[i * DIM + t];
    __syncthreads();

    // ---- Phase 1: distance from anchor to point t ----
    const float4* ej = reinterpret_cast<const float4*>(E + t * DIM);
    const float4* an = reinterpret_cast<const float4*>(anchor);
    float acc0 = 0.f, acc1 = 0.f;
#pragma unroll
    for (int k4 = 0; k4 < DIM / 4; k4 += 2) {
        float4 a0 = an[k4];
        float4 a1 = an[k4 + 1];
        float4 e0 = ej[k4];
        float4 e1 = ej[k4 + 1];
        float d;
        d = a0.x - e0.x; acc0 = fmaf(d, d, acc0);
        d = a0.y - e0.y; acc0 = fmaf(d, d, acc0);
        d = a0.z - e0.z; acc0 = fmaf(d, d, acc0);
        d = a0.w - e0.w; acc0 = fmaf(d, d, acc0);
        d = a1.x - e1.x; acc1 = fmaf(d, d, acc1);
        d = a1.y - e1.y; acc1 = fmaf(d, d, acc1);
        d = a1.z - e1.z; acc1 = fmaf(d, d, acc1);
        d = a1.w - e1.w; acc1 = fmaf(d, d, acc1);
    }
    const float dj = acc0 + acc1;

    // ---- Phase 2: warp-aggregated compaction into pos / neg lists ----
    const int li = labels[i];
    const bool same = (labels[t] == li);

    unsigned m_same = __ballot_sync(0xFFFFFFFFu, same);
    unsigned m_diff = ~m_same;
    unsigned lt = (1u << lane) - 1u;

    int base_pos = 0, base_neg = 0;
    if (lane == 0) {
        base_pos = atomicAdd(&cnts[0], __popc(m_same));
        base_neg = atomicAdd(&cnts[1], __popc(m_diff));
    }
    base_pos = __shfl_sync(0xFFFFFFFFu, base_pos, 0);
    base_neg = __shfl_sync(0xFFFFFFFFu, base_neg, 0);

    if (same) {
        spos[base_pos + __popc(m_same & lt)] = dj;
    } else {
        sneg[base_neg + __popc(m_diff & lt)] = dj;
    }
    __syncthreads();

    const int P = cnts[0];
    const int M = cnts[1];

    // ---- Phase 3: all (p, n) pairs ----
    float loss = 0.f;
    float cnt = 0.f;
    for (int p = 0; p < P; p++) {
        const float dpm = spos[p] + MARGIN;
        for (int n = t; n < M; n += N_PTS) {
            float L = dpm - sneg[n];
            if (L > 0.f && L < MARGIN) {
                loss += L;
                cnt += 1.f;
            }
        }
    }

    // ---- Block reduction (12 warps) ----
#pragma unroll
    for (int off = 16; off > 0; off >>= 1) {
        loss += __shfl_down_sync(0xFFFFFFFFu, loss, off);
        cnt  += __shfl_down_sync(0xFFFFFFFFu, cnt,  off);
    }
    if (lane == 0) { wl[warp] = loss; wc[warp] = cnt; }
    __syncthreads();
    if (warp == 0) {
        float l = (lane < 12) ? wl[lane] : 0.f;
        float c = (lane < 12) ? wc[lane] : 0.f;
#pragma unroll
        for (int off = 8; off > 0; off >>= 1) {
            l += __shfl_down_sync(0xFFFFFFFFu, l, off);
            c += __shfl_down_sync(0xFFFFFFFFu, c, off);
        }
        if (lane == 0) {
            atomicAdd(&out[0], l);
            atomicAdd(&out[1], c);
        }
    }
}

extern "C" void kernel_launch(void* const* d_in, const int* in_sizes, int n_in,
                              void* d_out, int out_size) {
    const float* embeddings = (const float*)d_in[0];
    const int* labels = (const int*)d_in[1];
    float* out = (float*)d_out;

    cudaMemsetAsync(out, 0, (size_t)out_size * sizeof(float));
    fused_triplet_kernel<<<N_PTS, N_PTS>>>(embeddings, labels, out);
}

// round 4
// speedup vs baseline: 1.0667x; 1.0667x over previous
#include <cuda_runtime.h>
#include <cuda_bf16.h>
#include <cstdint>

#define N_PTS 384
#define DIM 128
#define MARGIN 0.3f
#define ANCH 3
#define GRID_B 128
#define BLK 384
#define NWARP 12

// Cross-block accumulators (zero-initialized; last block resets them each run
// so the kernel is graph-replay deterministic without a memset node).
__device__ float g_acc[2];
__device__ unsigned int g_ticket;

__global__ __launch_bounds__(BLK) void fused_triplet_kernel(
    const float* __restrict__ E,
    const int* __restrict__ labels,
    float* __restrict__ out, int out_size) {

    const int t = threadIdx.x;
    const int lane = t & 31;
    const int warp = t >> 5;
    const int a0 = blockIdx.x * ANCH;

    __shared__ float sd[ANCH][N_PTS + 4];   // pad: avoid bank conflict on writes
    __shared__ float spos[ANCH][N_PTS];
    __shared__ float sneg[ANCH][N_PTS];
    __shared__ int slab[N_PTS];
    __shared__ int cnts[ANCH][2];
    __shared__ float wl[NWARP], wc[NWARP];

    if (t < ANCH * 2) ((int*)cnts)[t] = 0;
    slab[t] = labels[t];

    // Anchor chunks live in registers: lane l owns dims [4l, 4l+4).
    float4 A[ANCH];
#pragma unroll
    for (int a = 0; a < ANCH; a++)
        A[a] = *reinterpret_cast<const float4*>(E + (a0 + a) * DIM + lane * 4);

    // ---- Phase 1: distances, warp-per-row, coalesced ----
#pragma unroll 4
    for (int j = warp; j < N_PTS; j += NWARP) {
        float4 e = *reinterpret_cast<const float4*>(E + j * DIM + lane * 4);
        float p0, p1, p2;
        {
            float d;
            d = e.x - A[0].x; p0 = d * d;
            d = e.y - A[0].y; p0 = fmaf(d, d, p0);
            d = e.z - A[0].z; p0 = fmaf(d, d, p0);
            d = e.w - A[0].w; p0 = fmaf(d, d, p0);
            d = e.x - A[1].x; p1 = d * d;
            d = e.y - A[1].y; p1 = fmaf(d, d, p1);
            d = e.z - A[1].z; p1 = fmaf(d, d, p1);
            d = e.w - A[1].w; p1 = fmaf(d, d, p1);
            d = e.x - A[2].x; p2 = d * d;
            d = e.y - A[2].y; p2 = fmaf(d, d, p2);
            d = e.z - A[2].z; p2 = fmaf(d, d, p2);
            d = e.w - A[2].w; p2 = fmaf(d, d, p2);
        }
#pragma unroll
        for (int off = 16; off > 0; off >>= 1) {
            p0 += __shfl_xor_sync(0xFFFFFFFFu, p0, off);
            p1 += __shfl_xor_sync(0xFFFFFFFFu, p1, off);
            p2 += __shfl_xor_sync(0xFFFFFFFFu, p2, off);
        }
        if (lane == 0)      sd[0][j] = p0;
        else if (lane == 1) sd[1][j] = p1;
        else if (lane == 2) sd[2][j] = p2;
    }
    __syncthreads();

    // ---- Phase 2: warp-aggregated compaction into pos/neg lists ----
#pragma unroll
    for (int a = 0; a < ANCH; a++) {
        const int la = slab[a0 + a];
        const bool same = (slab[t] == la);
        const float dj = sd[a][t];

        unsigned ms = __ballot_sync(0xFFFFFFFFu, same);
        unsigned md = ~ms;
        unsigned lt = (1u << lane) - 1u;

        int bp = 0, bn = 0;
        if (lane == 0) {
            bp = atomicAdd(&cnts[a][0], __popc(ms));
            bn = atomicAdd(&cnts[a][1], __popc(md));
        }
        bp = __shfl_sync(0xFFFFFFFFu, bp, 0);
        bn = __shfl_sync(0xFFFFFFFFu, bn, 0);

        if (same) spos[a][bp + __popc(ms & lt)] = dj;
        else      sneg[a][bn + __popc(md & lt)] = dj;
    }
    __syncthreads();

    // ---- Phase 3: thread t holds its negative; iterate positives (LDS bcast) ----
    float loss = 0.f, cnt = 0.f;
#pragma unroll
    for (int a = 0; a < ANCH; a++) {
        const int P = cnts[a][0];
        const int M = cnts[a][1];
        if (t < M) {
            const float dn = sneg[a][t];
            for (int p = 0; p < P; p++) {
                float L = spos[a][p] + MARGIN - dn;
                if (L > 0.f && L < MARGIN) { loss += L; cnt += 1.f; }
            }
        }
    }

    // ---- Block reduction ----
#pragma unroll
    for (int off = 16; off > 0; off >>= 1) {
        loss += __shfl_down_sync(0xFFFFFFFFu, loss, off);
        cnt  += __shfl_down_sync(0xFFFFFFFFu, cnt,  off);
    }
    if (lane == 0) { wl[warp] = loss; wc[warp] = cnt; }
    __syncthreads();

    // ---- Cross-block accumulate + last-block writeout (no memset node) ----
    if (t == 0) {
        float l = 0.f, c = 0.f;
#pragma unroll
        for (int w = 0; w < NWARP; w++) { l += wl[w]; c += wc[w]; }
        atomicAdd(&g_acc[0], l);
        atomicAdd(&g_acc[1], c);
        __threadfence();
        unsigned done = atomicAdd(&g_ticket, 1u);
        if (done == GRID_B - 1) {
            __threadfence();
            out[0] = g_acc[0];
            out[1] = g_acc[1];
            for (int k = 2; k < out_size; k++) out[k] = 0.f;
            // reset for next graph replay
            g_acc[0] = 0.f;
            g_acc[1] = 0.f;
            g_ticket = 0u;
        }
    }
}

extern "C" void kernel_launch(void* const* d_in, const int* in_sizes, int n_in,
                              void* d_out, int out_size) {
    const float* embeddings = (const float*)d_in[0];
    const int* labels = (const int*)d_in[1];
    float* out = (float*)d_out;

    fused_triplet_kernel<<<GRID_B, BLK>>>(embeddings, labels, out, out_size);
}

// round 5
// speedup vs baseline: 2.5490x; 2.3897x over previous
#include <cuda_runtime.h>
#include <cuda_bf16.h>
#include <cstdint>

#define N_PTS 384
#define DIM 128
#define MARGIN 0.3f

// Gram matrix + norms scratch (no allocations allowed).
__device__ float g_gram[N_PTS * N_PTS];
__device__ float g_nrm[N_PTS];

// Cross-block accumulators for K2 (zero-init; last block resets each replay).
__device__ float g_acc[2];
__device__ unsigned int g_ticket;

// ---------------------------------------------------------------------------
// K1: Gram matrix G[i][j] = dot(E_i, E_j), 32x32 tiles, 2x2 register tile.
// Diagonal blocks also write norms[i] = G[i][i]. grid (12,12), 256 threads.
// ---------------------------------------------------------------------------
__global__ __launch_bounds__(256) void gram_kernel(const float* __restrict__ E,
                                                   float* __restrict__ G,
                                                   float* __restrict__ nrm) {
    __shared__ float As[32][132];
    __shared__ float Bs[32][132];

    const int bi = blockIdx.y * 32;
    const int bj = blockIdx.x * 32;
    const int t = threadIdx.x;

    const float4* E4 = reinterpret_cast<const float4*>(E);
    for (int v = t; v < 1024; v += 256) {
        int r = v >> 5;
        int c4 = v & 31;
        float4 a = E4[(bi + r) * 32 + c4];
        float4 b = E4[(bj + r) * 32 + c4];
        *reinterpret_cast<float4*>(&As[r][c4 * 4]) = a;
        *reinterpret_cast<float4*>(&Bs[r][c4 * 4]) = b;
    }
    __syncthreads();

    const int ti = t >> 4;
    const int tj = t & 15;

    float acc00 = 0.f, acc01 = 0.f, acc10 = 0.f, acc11 = 0.f;

#pragma unroll 8
    for (int k4 = 0; k4 < 32; k4++) {
        float4 a0 = *reinterpret_cast<const float4*>(&As[ti][k4 * 4]);
        float4 a1 = *reinterpret_cast<const float4*>(&As[ti + 16][k4 * 4]);
        float4 b0 = *reinterpret_cast<const float4*>(&Bs[tj][k4 * 4]);
        float4 b1 = *reinterpret_cast<const float4*>(&Bs[tj + 16][k4 * 4]);
        acc00 = fmaf(a0.x, b0.x, acc00);
        acc00 = fmaf(a0.y, b0.y, acc00);
        acc00 = fmaf(a0.z, b0.z, acc00);
        acc00 = fmaf(a0.w, b0.w, acc00);
        acc01 = fmaf(a0.x, b1.x, acc01);
        acc01 = fmaf(a0.y, b1.y, acc01);
        acc01 = fmaf(a0.z, b1.z, acc01);
        acc01 = fmaf(a0.w, b1.w, acc01);
        acc10 = fmaf(a1.x, b0.x, acc10);
        acc10 = fmaf(a1.y, b0.y, acc10);
        acc10 = fmaf(a1.z, b0.z, acc10);
        acc10 = fmaf(a1.w, b0.w, acc10);
        acc11 = fmaf(a1.x, b1.x, acc11);
        acc11 = fmaf(a1.y, b1.y, acc11);
        acc11 = fmaf(a1.z, b1.z, acc11);
        acc11 = fmaf(a1.w, b1.w, acc11);
    }

    const int gi0 = bi + ti, gi1 = bi + ti + 16;
    const int gj0 = bj + tj, gj1 = bj + tj + 16;
    G[gi0 * N_PTS + gj0] = acc00;
    G[gi0 * N_PTS + gj1] = acc01;
    G[gi1 * N_PTS + gj0] = acc10;
    G[gi1 * N_PTS + gj1] = acc11;

    if (blockIdx.x == blockIdx.y && ti == tj) {
        nrm[gi0] = acc00;
        nrm[gi1] = acc11;
    }
}

// ---------------------------------------------------------------------------
// K2: per-anchor triplet accumulation. 384 blocks x 384 threads.
// dist(i, t) = nrm[i] + nrm[t] - 2*G[i][t]  (reference's exact formula).
// Ballot-aggregated compaction, thread-holds-negative pair loop,
// device-side accumulator with last-block writeout + reset (no memset node).
// ---------------------------------------------------------------------------
__global__ __launch_bounds__(N_PTS) void triplet_kernel(
    const float* __restrict__ G,
    const float* __restrict__ nrm,
    const int* __restrict__ labels,
    float* __restrict__ out, int out_size) {

    const int i = blockIdx.x;
    const int t = threadIdx.x;
    const int lane = t & 31;
    const int warp = t >> 5;   // 12 warps

    __shared__ float spos[N_PTS];
    __shared__ float sneg[N_PTS];
    __shared__ int cnts[2];
    __shared__ float wl[12], wc[12];

    if (t < 2) cnts[t] = 0;

    const int li = __ldg(&labels[i]);
    const float ni = __ldg(&nrm[i]);

    const float dj = ni + nrm[t] - 2.f * G[i * N_PTS + t];
    const bool same = (labels[t] == li);
    __syncthreads();   // cnts ready

    unsigned ms = __ballot_sync(0xFFFFFFFFu, same);
    unsigned md = ~ms;
    unsigned lt = (1u << lane) - 1u;

    int bp = 0, bn = 0;
    if (lane == 0) {
        bp = atomicAdd(&cnts[0], __popc(ms));
        bn = atomicAdd(&cnts[1], __popc(md));
    }
    bp = __shfl_sync(0xFFFFFFFFu, bp, 0);
    bn = __shfl_sync(0xFFFFFFFFu, bn, 0);

    if (same) spos[bp + __popc(ms & lt)] = dj;
    else      sneg[bn + __popc(md & lt)] = dj;
    __syncthreads();

    const int P = cnts[0];
    const int M = cnts[1];

    float loss = 0.f, cnt = 0.f;
    if (t < M) {
        const float dn = sneg[t];
        for (int p = 0; p < P; p++) {
            float L = spos[p] + MARGIN - dn;
            if (L > 0.f && L < MARGIN) { loss += L; cnt += 1.f; }
        }
    }

#pragma unroll
    for (int off = 16; off > 0; off >>= 1) {
        loss += __shfl_down_sync(0xFFFFFFFFu, loss, off);
        cnt  += __shfl_down_sync(0xFFFFFFFFu, cnt,  off);
    }
    if (lane == 0) { wl[warp] = loss; wc[warp] = cnt; }
    __syncthreads();

    if (t == 0) {
        float l = 0.f, c = 0.f;
#pragma unroll
        for (int w = 0; w < 12; w++) { l += wl[w]; c += wc[w]; }
        atomicAdd(&g_acc[0], l);
        atomicAdd(&g_acc[1], c);
        __threadfence();
        unsigned done = atomicAdd(&g_ticket, 1u);
        if (done == N_PTS - 1) {
            __threadfence();
            out[0] = g_acc[0];
            out[1] = g_acc[1];
            for (int k = 2; k < out_size; k++) out[k] = 0.f;
            g_acc[0] = 0.f;
            g_acc[1] = 0.f;
            g_ticket = 0u;
        }
    }
}

extern "C" void kernel_launch(void* const* d_in, const int* in_sizes, int n_in,
                              void* d_out, int out_size) {
    const float* embeddings = (const float*)d_in[0];
    const int* labels = (const int*)d_in[1];
    float* out = (float*)d_out;

    float *G, *nrm;
    cudaGetSymbolAddress((void**)&G, g_gram);
    cudaGetSymbolAddress((void**)&nrm, g_nrm);

    dim3 grid1(12, 12);
    gram_kernel<<<grid1, 256>>>(embeddings, G, nrm);
    triplet_kernel<<<N_PTS, N_PTS>>>(G, nrm, labels, out, out_size);
}